// round 3
// baseline (speedup 1.0000x reference)
#include <cuda_runtime.h>
#include <math.h>

#define F0   128
#define HID  64
#define NG   64
#define NC   10
#define MAXN 100000
#define MAXE 1600000

// ---- scratch (no allocs allowed) ----
__device__ int   g_is64;
__device__ float g_deg [MAXN];
__device__ float g_dinv[MAXN];
__device__ int   g_src [MAXE];
__device__ int   g_dst [MAXE];
__device__ float g_norm[MAXE];
__device__ float g_h   [MAXN * HID];   // h = act(in) @ W
__device__ float g_agg [MAXN * HID];   // pre-relu layer output
__device__ float g_pool[NG * HID];
__device__ float g_cnt [NG];

// index fetch honoring runtime-detected dtype (element index, not byte)
__device__ __forceinline__ int fetch_idx(const void* p, long long i) {
    if (g_is64) return (int)((const long long*)p)[i];
    return ((const int*)p)[i];
}

// ---------------- dtype detection ----------------
// int64 values < 2^31: every odd int32 word is 0. int32 random data: ~never.
__global__ void k_detect(const int* __restrict__ ei) {
    if (threadIdx.x == 0 && blockIdx.x == 0) {
        int acc = 0;
        #pragma unroll 8
        for (int i = 1; i < 2048; i += 2) acc |= ei[i];
        g_is64 = (acc == 0) ? 1 : 0;
    }
}

// ---------------- degree / norm precompute ----------------
__global__ void k_deg_init(int n) {
    int i = blockIdx.x * blockDim.x + threadIdx.x;
    if (i < n) g_deg[i] = 1.0f;           // self-loop contributes 1
}
__global__ void k_deg(const void* __restrict__ ei, int e) {
    int i = blockIdx.x * blockDim.x + threadIdx.x;
    if (i < e) {
        int d = fetch_idx(ei, (long long)e + i);   // dst row
        atomicAdd(&g_deg[d], 1.0f);
    }
}
__global__ void k_dinv(int n) {
    int i = blockIdx.x * blockDim.x + threadIdx.x;
    if (i < n) g_dinv[i] = rsqrtf(g_deg[i]);
}
__global__ void k_norm(const void* __restrict__ ei, int e) {
    int i = blockIdx.x * blockDim.x + threadIdx.x;
    if (i < e) {
        int s = fetch_idx(ei, i);
        int d = fetch_idx(ei, (long long)e + i);
        g_src[i] = s; g_dst[i] = d;
        g_norm[i] = g_dinv[s] * g_dinv[d];
    }
}
__global__ void k_zero_pool() {
    int i = blockIdx.x * blockDim.x + threadIdx.x;
    if (i < NG * HID) g_pool[i] = 0.0f;
    if (i < NG)       g_cnt[i]  = 0.0f;
}

// ---------------- GEMM: g_h = act(in) @ W  (in: [n,F_IN], W: [F_IN,64]) ----
template<int F_IN, bool RELU, bool USE_AGG>
__global__ void __launch_bounds__(256) k_gemm(const float* __restrict__ in,
                                              const float* __restrict__ W, int n) {
    __shared__ float Ws[F_IN * HID];
    __shared__ float xs[32 * F_IN];
    const float* srcp = USE_AGG ? g_agg : in;
    const int tid = threadIdx.x;
    const int base = blockIdx.x * 32;

    #pragma unroll 4
    for (int i = tid; i < F_IN * HID; i += 256) Ws[i] = W[i];

    for (int i = tid; i < 32 * F_IN; i += 256) {
        int row = base + (i / F_IN);
        float v = 0.0f;
        if (row < n) {
            v = srcp[(size_t)row * F_IN + (i & (F_IN - 1))];
            if (RELU) v = fmaxf(v, 0.0f);
        }
        xs[i] = v;
    }
    __syncthreads();

    const int c  = tid & 63;     // output feature
    const int rg = tid >> 6;     // row group (whole warp shares rg)
    float acc[8];
    #pragma unroll
    for (int r = 0; r < 8; r++) acc[r] = 0.0f;

    #pragma unroll 4
    for (int k = 0; k < F_IN; k++) {
        float wk = Ws[k * HID + c];
        #pragma unroll
        for (int r = 0; r < 8; r++)
            acc[r] += xs[(rg * 8 + r) * F_IN + k] * wk;
    }

    #pragma unroll
    for (int r = 0; r < 8; r++) {
        int row = base + rg * 8 + r;
        if (row < n) g_h[(size_t)row * HID + c] = acc[r];
    }
}

// ---------------- agg init: self-loop + bias ----------------
__global__ void k_selfbias(const float* __restrict__ b, int n) {
    int idx = blockIdx.x * blockDim.x + threadIdx.x;   // over n*16 float4s
    if (idx >= n * 16) return;
    int i = idx >> 4, q = idx & 15;
    float di = g_dinv[i];
    float nm = di * di;
    float4 h = ((const float4*)g_h)[idx];
    float4 bb = ((const float4*)b)[q];
    float4 o;
    o.x = fmaf(h.x, nm, bb.x);
    o.y = fmaf(h.y, nm, bb.y);
    o.z = fmaf(h.z, nm, bb.z);
    o.w = fmaf(h.w, nm, bb.w);
    ((float4*)g_agg)[idx] = o;
}

// ---------------- edge aggregation: agg[dst] += norm * h[src] ----------------
__global__ void __launch_bounds__(256) k_edge(int e) {
    int idx = blockIdx.x * blockDim.x + threadIdx.x;   // 16 threads per edge
    if (idx >= e * 16) return;
    int ei = idx >> 4, q = idx & 15;
    int s = g_src[ei], d = g_dst[ei];
    float nm = g_norm[ei];
    float4 v = ((const float4*)g_h)[s * 16 + q];
    float* ap = &g_agg[d * 64 + q * 4];
    atomicAdd(ap + 0, v.x * nm);
    atomicAdd(ap + 1, v.y * nm);
    atomicAdd(ap + 2, v.z * nm);
    atomicAdd(ap + 3, v.w * nm);
}

// ---------------- pooling: mean over sorted batch, relu on load ----------------
__global__ void k_pool(const void* __restrict__ batch, int n) {
    int idx = blockIdx.x * blockDim.x + threadIdx.x;
    int nstrips = (n + 63) / 64;
    if (idx >= nstrips * 16) return;
    int strip = idx >> 4, q = idx & 15;
    int i0 = strip * 64;
    int i1 = min(i0 + 64, n);
    float4 acc = make_float4(0.f, 0.f, 0.f, 0.f);
    float cnt = 0.f;
    int gcur = fetch_idx(batch, i0);
    for (int i = i0; i < i1; i++) {
        int g = fetch_idx(batch, i);
        if (g != gcur) {
            float* pp = &g_pool[gcur * 64 + q * 4];
            atomicAdd(pp + 0, acc.x); atomicAdd(pp + 1, acc.y);
            atomicAdd(pp + 2, acc.z); atomicAdd(pp + 3, acc.w);
            if (q == 0) atomicAdd(&g_cnt[gcur], cnt);
            acc = make_float4(0.f, 0.f, 0.f, 0.f); cnt = 0.f; gcur = g;
        }
        float4 h = ((const float4*)g_agg)[i * 16 + q];
        acc.x += fmaxf(h.x, 0.f);
        acc.y += fmaxf(h.y, 0.f);
        acc.z += fmaxf(h.z, 0.f);
        acc.w += fmaxf(h.w, 0.f);
        cnt += 1.0f;
    }
    float* pp = &g_pool[gcur * 64 + q * 4];
    atomicAdd(pp + 0, acc.x); atomicAdd(pp + 1, acc.y);
    atomicAdd(pp + 2, acc.z); atomicAdd(pp + 3, acc.w);
    if (q == 0) atomicAdd(&g_cnt[gcur], cnt);
}

// ---------------- final: linear + softmax ----------------
__global__ void k_final(const float* __restrict__ Wl, const float* __restrict__ bl,
                        float* __restrict__ out) {
    int g = threadIdx.x;
    if (g >= NG) return;
    float inv = 1.0f / fmaxf(g_cnt[g], 1.0f);
    float logits[NC];
    #pragma unroll
    for (int c = 0; c < NC; c++) logits[c] = bl[c];
    for (int f = 0; f < HID; f++) {
        float p = g_pool[g * HID + f] * inv;
        #pragma unroll
        for (int c = 0; c < NC; c++) logits[c] = fmaf(p, Wl[f * NC + c], logits[c]);
    }
    float mx = logits[0];
    #pragma unroll
    for (int c = 1; c < NC; c++) mx = fmaxf(mx, logits[c]);
    float s = 0.0f;
    #pragma unroll
    for (int c = 0; c < NC; c++) { logits[c] = expf(logits[c] - mx); s += logits[c]; }
    float is = 1.0f / s;
    #pragma unroll
    for (int c = 0; c < NC; c++) out[g * NC + c] = logits[c] * is;
}

extern "C" void kernel_launch(void* const* d_in, const int* in_sizes, int n_in,
                              void* d_out, int out_size) {
    const float* x     = (const float*)d_in[0];
    const void*  ei    = d_in[1];
    const void*  batch = d_in[2];
    const float* W1 = (const float*)d_in[3];
    const float* b1 = (const float*)d_in[4];
    const float* W2 = (const float*)d_in[5];
    const float* b2 = (const float*)d_in[6];
    const float* W3 = (const float*)d_in[7];
    const float* b3 = (const float*)d_in[8];
    const float* Wl = (const float*)d_in[9];
    const float* bl = (const float*)d_in[10];

    const int n = in_sizes[0] / F0;
    const int E = in_sizes[1] / 2;

    const int TB = 256;
    // dtype detect, then degree / norm
    k_detect<<<1, 32>>>((const int*)ei);
    k_deg_init<<<(n + TB - 1) / TB, TB>>>(n);
    k_deg<<<(E + TB - 1) / TB, TB>>>(ei, E);
    k_dinv<<<(n + TB - 1) / TB, TB>>>(n);
    k_norm<<<(E + TB - 1) / TB, TB>>>(ei, E);
    k_zero_pool<<<(NG * HID + TB - 1) / TB, TB>>>();

    const int gGemm = (n + 31) / 32;
    const int gN16  = (n * 16 + TB - 1) / TB;
    const int gE16  = (E * 16 + TB - 1) / TB;

    // layer 1: in = x (128 feats, no relu)
    k_gemm<F0, false, false><<<gGemm, TB>>>(x, W1, n);
    k_selfbias<<<gN16, TB>>>(b1, n);
    k_edge<<<gE16, TB>>>(E);
    // layer 2: in = relu(g_agg)
    k_gemm<HID, true, true><<<gGemm, TB>>>(x, W2, n);
    k_selfbias<<<gN16, TB>>>(b2, n);
    k_edge<<<gE16, TB>>>(E);
    // layer 3
    k_gemm<HID, true, true><<<gGemm, TB>>>(x, W3, n);
    k_selfbias<<<gN16, TB>>>(b3, n);
    k_edge<<<gE16, TB>>>(E);

    // pooling + head
    int nstrips = (n + 63) / 64;
    k_pool<<<(nstrips * 16 + TB - 1) / TB, TB>>>(batch, n);
    k_final<<<1, NG>>>(Wl, bl, (float*)d_out);
}

// round 5
// speedup vs baseline: 1.6726x; 1.6726x over previous
#include <cuda_runtime.h>
#include <math.h>

#define F0   128
#define HID  64
#define NG   64
#define NC   10
#define MAXN 100000
#define MAXE 1600000

// ---- scratch (no allocs allowed) ----
__device__ int   g_is64;
__device__ float g_deg [MAXN];
__device__ float g_dinv[MAXN];
__device__ int   g_src [MAXE];
__device__ int   g_dst [MAXE];
__device__ float g_norm[MAXE];
__device__ float g_h   [MAXN * HID];   // h = act(in) @ W
__device__ float g_agg [MAXN * HID];   // pre-relu layer output
__device__ float g_pool[NG * HID];
__device__ float g_cnt [NG];

// index fetch honoring runtime-detected dtype (element index, not byte)
__device__ __forceinline__ int fetch_idx(const void* p, long long i) {
    if (g_is64) return (int)((const long long*)p)[i];
    return ((const int*)p)[i];
}

// ---------------- dtype detection ----------------
// int64 values < 2^31: every odd int32 word is 0. int32 random data: ~never.
__global__ void k_detect(const int* __restrict__ ei) {
    if (threadIdx.x == 0 && blockIdx.x == 0) {
        int acc = 0;
        #pragma unroll 8
        for (int i = 1; i < 2048; i += 2) acc |= ei[i];
        g_is64 = (acc == 0) ? 1 : 0;
    }
}

// ---------------- degree / norm precompute ----------------
__global__ void k_deg_init(int n) {
    int i = blockIdx.x * blockDim.x + threadIdx.x;
    if (i < n) g_deg[i] = 1.0f;           // self-loop contributes 1
}
__global__ void k_deg(const void* __restrict__ ei, int e) {
    int i = blockIdx.x * blockDim.x + threadIdx.x;
    if (i < e) {
        int d = fetch_idx(ei, (long long)e + i);   // dst row
        atomicAdd(&g_deg[d], 1.0f);
    }
}
__global__ void k_dinv(int n) {
    int i = blockIdx.x * blockDim.x + threadIdx.x;
    if (i < n) g_dinv[i] = rsqrtf(g_deg[i]);
}
__global__ void k_norm(const void* __restrict__ ei, int e) {
    int i = blockIdx.x * blockDim.x + threadIdx.x;
    if (i < e) {
        int s = fetch_idx(ei, i);
        int d = fetch_idx(ei, (long long)e + i);
        g_src[i] = s; g_dst[i] = d;
        g_norm[i] = g_dinv[s] * g_dinv[d];
    }
}
__global__ void k_zero_pool() {
    int i = blockIdx.x * blockDim.x + threadIdx.x;
    if (i < NG * HID) g_pool[i] = 0.0f;
    if (i < NG)       g_cnt[i]  = 0.0f;
}

// ---------------- GEMM: g_h = act(in) @ W ; g_agg = h*dinv^2 + b ----------
template<int F_IN, bool RELU, bool USE_AGG>
__global__ void __launch_bounds__(256) k_gemm(const float* __restrict__ in,
                                              const float* __restrict__ W,
                                              const float* __restrict__ b, int n) {
    __shared__ float Ws[F_IN * HID];
    __shared__ float xs[32 * F_IN];
    const float* srcp = USE_AGG ? g_agg : in;
    const int tid = threadIdx.x;
    const int base = blockIdx.x * 32;

    #pragma unroll 4
    for (int i = tid; i < F_IN * HID; i += 256) Ws[i] = W[i];

    for (int i = tid; i < 32 * F_IN; i += 256) {
        int row = base + (i / F_IN);
        float v = 0.0f;
        if (row < n) {
            v = srcp[(size_t)row * F_IN + (i & (F_IN - 1))];
            if (RELU) v = fmaxf(v, 0.0f);
        }
        xs[i] = v;
    }
    __syncthreads();

    const int c  = tid & 63;     // output feature
    const int rg = tid >> 6;     // row group (whole warp shares rg)
    const float bc = b[c];
    float acc[8];
    #pragma unroll
    for (int r = 0; r < 8; r++) acc[r] = 0.0f;

    #pragma unroll 4
    for (int k = 0; k < F_IN; k++) {
        float wk = Ws[k * HID + c];
        #pragma unroll
        for (int r = 0; r < 8; r++)
            acc[r] += xs[(rg * 8 + r) * F_IN + k] * wk;
    }

    #pragma unroll
    for (int r = 0; r < 8; r++) {
        int row = base + rg * 8 + r;
        if (row < n) {
            g_h[(size_t)row * HID + c] = acc[r];
            float di = g_dinv[row];
            g_agg[(size_t)row * HID + c] = fmaf(acc[r], di * di, bc);
        }
    }
}

// ---------------- edge aggregation: agg[dst] += norm * h[src] ----------------
// 16 threads per edge, one red.global.add.v4.f32 (REDG.128) each.
__global__ void __launch_bounds__(256) k_edge(int e) {
    int idx = blockIdx.x * blockDim.x + threadIdx.x;
    if (idx >= e * 16) return;
    int ei = idx >> 4, q = idx & 15;
    int s = g_src[ei], d = g_dst[ei];
    float nm = g_norm[ei];
    float4 v = ((const float4*)g_h)[s * 16 + q];
    float* ap = &g_agg[d * 64 + q * 4];
    asm volatile("red.global.add.v4.f32 [%0], {%1, %2, %3, %4};"
                 :: "l"(ap), "f"(v.x * nm), "f"(v.y * nm), "f"(v.z * nm), "f"(v.w * nm)
                 : "memory");
}

// ---------------- pooling: mean over sorted batch, relu on load ----------------
__global__ void k_pool(const void* __restrict__ batch, int n) {
    int idx = blockIdx.x * blockDim.x + threadIdx.x;
    int nstrips = (n + 63) / 64;
    if (idx >= nstrips * 16) return;
    int strip = idx >> 4, q = idx & 15;
    int i0 = strip * 64;
    int i1 = min(i0 + 64, n);
    float4 acc = make_float4(0.f, 0.f, 0.f, 0.f);
    float cnt = 0.f;
    int gcur = fetch_idx(batch, i0);
    for (int i = i0; i < i1; i++) {
        int g = fetch_idx(batch, i);
        if (g != gcur) {
            float* pp = &g_pool[gcur * 64 + q * 4];
            atomicAdd(pp + 0, acc.x); atomicAdd(pp + 1, acc.y);
            atomicAdd(pp + 2, acc.z); atomicAdd(pp + 3, acc.w);
            if (q == 0) atomicAdd(&g_cnt[gcur], cnt);
            acc = make_float4(0.f, 0.f, 0.f, 0.f); cnt = 0.f; gcur = g;
        }
        float4 h = ((const float4*)g_agg)[i * 16 + q];
        acc.x += fmaxf(h.x, 0.f);
        acc.y += fmaxf(h.y, 0.f);
        acc.z += fmaxf(h.z, 0.f);
        acc.w += fmaxf(h.w, 0.f);
        cnt += 1.0f;
    }
    float* pp = &g_pool[gcur * 64 + q * 4];
    atomicAdd(pp + 0, acc.x); atomicAdd(pp + 1, acc.y);
    atomicAdd(pp + 2, acc.z); atomicAdd(pp + 3, acc.w);
    if (q == 0) atomicAdd(&g_cnt[gcur], cnt);
}

// ---------------- final: linear + softmax ----------------
__global__ void k_final(const float* __restrict__ Wl, const float* __restrict__ bl,
                        float* __restrict__ out) {
    int g = threadIdx.x;
    if (g >= NG) return;
    float inv = 1.0f / fmaxf(g_cnt[g], 1.0f);
    float logits[NC];
    #pragma unroll
    for (int c = 0; c < NC; c++) logits[c] = bl[c];
    for (int f = 0; f < HID; f++) {
        float p = g_pool[g * HID + f] * inv;
        #pragma unroll
        for (int c = 0; c < NC; c++) logits[c] = fmaf(p, Wl[f * NC + c], logits[c]);
    }
    float mx = logits[0];
    #pragma unroll
    for (int c = 1; c < NC; c++) mx = fmaxf(mx, logits[c]);
    float s = 0.0f;
    #pragma unroll
    for (int c = 0; c < NC; c++) { logits[c] = expf(logits[c] - mx); s += logits[c]; }
    float is = 1.0f / s;
    #pragma unroll
    for (int c = 0; c < NC; c++) out[g * NC + c] = logits[c] * is;
}

extern "C" void kernel_launch(void* const* d_in, const int* in_sizes, int n_in,
                              void* d_out, int out_size) {
    const float* x     = (const float*)d_in[0];
    const void*  ei    = d_in[1];
    const void*  batch = d_in[2];
    const float* W1 = (const float*)d_in[3];
    const float* b1 = (const float*)d_in[4];
    const float* W2 = (const float*)d_in[5];
    const float* b2 = (const float*)d_in[6];
    const float* W3 = (const float*)d_in[7];
    const float* b3 = (const float*)d_in[8];
    const float* Wl = (const float*)d_in[9];
    const float* bl = (const float*)d_in[10];

    const int n = in_sizes[0] / F0;
    const int E = in_sizes[1] / 2;

    const int TB = 256;
    // dtype detect, then degree / norm
    k_detect<<<1, 32>>>((const int*)ei);
    k_deg_init<<<(n + TB - 1) / TB, TB>>>(n);
    k_deg<<<(E + TB - 1) / TB, TB>>>(ei, E);
    k_dinv<<<(n + TB - 1) / TB, TB>>>(n);
    k_norm<<<(E + TB - 1) / TB, TB>>>(ei, E);
    k_zero_pool<<<(NG * HID + TB - 1) / TB, TB>>>();

    const int gGemm = (n + 31) / 32;
    const int gE16  = (E * 16 + TB - 1) / TB;

    // layer 1: in = x (128 feats, no relu)
    k_gemm<F0, false, false><<<gGemm, TB>>>(x, W1, b1, n);
    k_edge<<<gE16, TB>>>(E);
    // layer 2: in = relu(g_agg)
    k_gemm<HID, true, true><<<gGemm, TB>>>(x, W2, b2, n);
    k_edge<<<gE16, TB>>>(E);
    // layer 3
    k_gemm<HID, true, true><<<gGemm, TB>>>(x, W3, b3, n);
    k_edge<<<gE16, TB>>>(E);

    // pooling + head
    int nstrips = (n + 63) / 64;
    k_pool<<<(nstrips * 16 + TB - 1) / TB, TB>>>(batch, n);
    k_final<<<1, NG>>>(Wl, bl, (float*)d_out);
}

// round 6
// speedup vs baseline: 2.2382x; 1.3382x over previous
#include <cuda_runtime.h>
#include <math.h>

#define F0   128
#define HID  64
#define NG   64
#define NC   10
#define MAXN 100000
#define MAXE 1600000
#define SCAN_B 512
#define MAX_PART 256

// ---- scratch (no allocs allowed) ----
__device__ int   g_is64;
__device__ int   g_idc [MAXN];          // in-degree (int, excl. self-loop)
__device__ float g_dinv[MAXN];
__device__ int   g_rowstart[MAXN + 1];
__device__ int   g_cursor[MAXN];
__device__ int   g_part[MAX_PART];
__device__ int   g_csrc [MAXE];         // CSR: src per slot
__device__ float g_cnorm[MAXE];         // CSR: norm per slot
__device__ float g_h   [MAXN * HID];    // h = act(in) @ W
__device__ float g_agg [MAXN * HID];    // layer output (pre-relu)
__device__ float g_pool[NG * HID];
__device__ float g_cnt [NG];

__device__ __forceinline__ int fetch_idx(const void* p, long long i) {
    if (g_is64) return (int)((const long long*)p)[i];
    return ((const int*)p)[i];
}

// ---------------- dtype detection ----------------
__global__ void k_detect(const int* __restrict__ ei) {
    if (threadIdx.x == 0 && blockIdx.x == 0) {
        int acc = 0;
        #pragma unroll 8
        for (int i = 1; i < 2048; i += 2) acc |= ei[i];
        g_is64 = (acc == 0) ? 1 : 0;
    }
}

// ---------------- degree ----------------
__global__ void k_zero_n(int n) {
    int i = blockIdx.x * blockDim.x + threadIdx.x;
    if (i < n) g_idc[i] = 0;
}
__global__ void k_deg(const void* __restrict__ ei, int e) {
    int i = blockIdx.x * blockDim.x + threadIdx.x;
    if (i < e) atomicAdd(&g_idc[fetch_idx(ei, (long long)e + i)], 1);
}
__global__ void k_dinv(int n) {
    int i = blockIdx.x * blockDim.x + threadIdx.x;
    if (i < n) g_dinv[i] = rsqrtf((float)(g_idc[i] + 1));
}

// ---------------- exclusive scan of g_idc -> g_rowstart ----------------
__global__ void k_scan1(int n) {
    __shared__ int s[SCAN_B];
    int i = blockIdx.x * SCAN_B + threadIdx.x;
    int v = (i < n) ? g_idc[i] : 0;
    s[threadIdx.x] = v;
    __syncthreads();
    int incl = v;
    #pragma unroll
    for (int d = 1; d < SCAN_B; d <<= 1) {
        int t = (threadIdx.x >= d) ? s[threadIdx.x - d] : 0;
        __syncthreads();
        incl += t;
        s[threadIdx.x] = incl;
        __syncthreads();
    }
    if (i < n) g_rowstart[i] = incl - v;           // block-local exclusive
    if (threadIdx.x == SCAN_B - 1) g_part[blockIdx.x] = incl;
}
__global__ void k_scan2(int nb) {
    __shared__ int s[MAX_PART];
    int v = (threadIdx.x < nb) ? g_part[threadIdx.x] : 0;
    s[threadIdx.x] = v;
    __syncthreads();
    int incl = v;
    #pragma unroll
    for (int d = 1; d < MAX_PART; d <<= 1) {
        int t = (threadIdx.x >= d) ? s[threadIdx.x - d] : 0;
        __syncthreads();
        incl += t;
        s[threadIdx.x] = incl;
        __syncthreads();
    }
    if (threadIdx.x < nb) g_part[threadIdx.x] = incl - v;   // exclusive
}
__global__ void k_scan3(int n, int e) {
    int i = blockIdx.x * blockDim.x + threadIdx.x;
    if (i < n) {
        int r = g_rowstart[i] + g_part[blockIdx.x * blockDim.x / SCAN_B + 0];
        // careful: block offset index = i / SCAN_B
        r = g_rowstart[i] + g_part[i / SCAN_B] - g_part[i / SCAN_B] + g_part[i / SCAN_B];
        r = g_rowstart[i] + g_part[i / SCAN_B];
        g_rowstart[i] = r;
        g_cursor[i] = r;
    }
    if (i == 0) g_rowstart[n] = e;
}

// ---------------- CSR fill: compute norm, scatter (src,norm) ----------------
__global__ void k_fill(const void* __restrict__ ei, int e) {
    int i = blockIdx.x * blockDim.x + threadIdx.x;
    if (i < e) {
        int s = fetch_idx(ei, i);
        int d = fetch_idx(ei, (long long)e + i);
        int pos = atomicAdd(&g_cursor[d], 1);
        g_csrc[pos]  = s;
        g_cnorm[pos] = g_dinv[s] * g_dinv[d];
    }
}

__global__ void k_zero_pool() {
    int i = blockIdx.x * blockDim.x + threadIdx.x;
    if (i < NG * HID) g_pool[i] = 0.0f;
    if (i < NG)       g_cnt[i]  = 0.0f;
}

// ---------------- GEMM: g_h = act(in) @ W ----------------
template<int F_IN, bool RELU, bool USE_AGG>
__global__ void __launch_bounds__(256) k_gemm(const float* __restrict__ in,
                                              const float* __restrict__ W, int n) {
    __shared__ float Ws[F_IN * HID];
    __shared__ float xs[32 * F_IN];
    const float* srcp = USE_AGG ? g_agg : in;
    const int tid = threadIdx.x;
    const int base = blockIdx.x * 32;

    #pragma unroll 4
    for (int i = tid; i < F_IN * HID; i += 256) Ws[i] = W[i];

    for (int i = tid; i < 32 * F_IN; i += 256) {
        int row = base + (i / F_IN);
        float v = 0.0f;
        if (row < n) {
            v = srcp[(size_t)row * F_IN + (i & (F_IN - 1))];
            if (RELU) v = fmaxf(v, 0.0f);
        }
        xs[i] = v;
    }
    __syncthreads();

    const int c  = tid & 63;
    const int rg = tid >> 6;
    float acc[8];
    #pragma unroll
    for (int r = 0; r < 8; r++) acc[r] = 0.0f;

    #pragma unroll 4
    for (int k = 0; k < F_IN; k++) {
        float wk = Ws[k * HID + c];
        #pragma unroll
        for (int r = 0; r < 8; r++)
            acc[r] += xs[(rg * 8 + r) * F_IN + k] * wk;
    }

    #pragma unroll
    for (int r = 0; r < 8; r++) {
        int row = base + rg * 8 + r;
        if (row < n) g_h[(size_t)row * HID + c] = acc[r];
    }
}

// ---------------- CSR gather: agg[i] = dinv_i^2*h[i] + b + sum norm*h[src] ---
__global__ void __launch_bounds__(256) k_gather(const float* __restrict__ b, int n) {
    int idx = blockIdx.x * blockDim.x + threadIdx.x;   // n*16 threads
    if (idx >= n * 16) return;
    int i = idx >> 4, q = idx & 15;
    int beg = g_rowstart[i], end = g_rowstart[i + 1];
    float di = g_dinv[i];
    float nm0 = di * di;
    float4 hh = ((const float4*)g_h)[idx];
    float4 bb = ((const float4*)b)[q];
    float4 acc;
    acc.x = fmaf(hh.x, nm0, bb.x);
    acc.y = fmaf(hh.y, nm0, bb.y);
    acc.z = fmaf(hh.z, nm0, bb.z);
    acc.w = fmaf(hh.w, nm0, bb.w);
    #pragma unroll 4
    for (int p = beg; p < end; p++) {
        int s = g_csrc[p];           // broadcast across the 16 lanes
        float nm = g_cnorm[p];
        float4 v = ((const float4*)g_h)[s * 16 + q];
        acc.x = fmaf(v.x, nm, acc.x);
        acc.y = fmaf(v.y, nm, acc.y);
        acc.z = fmaf(v.z, nm, acc.z);
        acc.w = fmaf(v.w, nm, acc.w);
    }
    ((float4*)g_agg)[idx] = acc;
}

// ---------------- pooling: mean over sorted batch, relu on load -------------
__global__ void k_pool(const void* __restrict__ batch, int n) {
    int idx = blockIdx.x * blockDim.x + threadIdx.x;
    int nstrips = (n + 63) / 64;
    if (idx >= nstrips * 16) return;
    int strip = idx >> 4, q = idx & 15;
    int i0 = strip * 64;
    int i1 = min(i0 + 64, n);
    float4 acc = make_float4(0.f, 0.f, 0.f, 0.f);
    float cnt = 0.f;
    int gcur = fetch_idx(batch, i0);
    for (int i = i0; i < i1; i++) {
        int g = fetch_idx(batch, i);
        if (g != gcur) {
            float* pp = &g_pool[gcur * 64 + q * 4];
            atomicAdd(pp + 0, acc.x); atomicAdd(pp + 1, acc.y);
            atomicAdd(pp + 2, acc.z); atomicAdd(pp + 3, acc.w);
            if (q == 0) atomicAdd(&g_cnt[gcur], cnt);
            acc = make_float4(0.f, 0.f, 0.f, 0.f); cnt = 0.f; gcur = g;
        }
        float4 h = ((const float4*)g_agg)[i * 16 + q];
        acc.x += fmaxf(h.x, 0.f);
        acc.y += fmaxf(h.y, 0.f);
        acc.z += fmaxf(h.z, 0.f);
        acc.w += fmaxf(h.w, 0.f);
        cnt += 1.0f;
    }
    float* pp = &g_pool[gcur * 64 + q * 4];
    atomicAdd(pp + 0, acc.x); atomicAdd(pp + 1, acc.y);
    atomicAdd(pp + 2, acc.z); atomicAdd(pp + 3, acc.w);
    if (q == 0) atomicAdd(&g_cnt[gcur], cnt);
}

// ---------------- final: linear + softmax ----------------
__global__ void k_final(const float* __restrict__ Wl, const float* __restrict__ bl,
                        float* __restrict__ out) {
    int g = threadIdx.x;
    if (g >= NG) return;
    float inv = 1.0f / fmaxf(g_cnt[g], 1.0f);
    float logits[NC];
    #pragma unroll
    for (int c = 0; c < NC; c++) logits[c] = bl[c];
    for (int f = 0; f < HID; f++) {
        float p = g_pool[g * HID + f] * inv;
        #pragma unroll
        for (int c = 0; c < NC; c++) logits[c] = fmaf(p, Wl[f * NC + c], logits[c]);
    }
    float mx = logits[0];
    #pragma unroll
    for (int c = 1; c < NC; c++) mx = fmaxf(mx, logits[c]);
    float s = 0.0f;
    #pragma unroll
    for (int c = 0; c < NC; c++) { logits[c] = expf(logits[c] - mx); s += logits[c]; }
    float is = 1.0f / s;
    #pragma unroll
    for (int c = 0; c < NC; c++) out[g * NC + c] = logits[c] * is;
}

extern "C" void kernel_launch(void* const* d_in, const int* in_sizes, int n_in,
                              void* d_out, int out_size) {
    const float* x     = (const float*)d_in[0];
    const void*  ei    = d_in[1];
    const void*  batch = d_in[2];
    const float* W1 = (const float*)d_in[3];
    const float* b1 = (const float*)d_in[4];
    const float* W2 = (const float*)d_in[5];
    const float* b2 = (const float*)d_in[6];
    const float* W3 = (const float*)d_in[7];
    const float* b3 = (const float*)d_in[8];
    const float* Wl = (const float*)d_in[9];
    const float* bl = (const float*)d_in[10];

    const int n = in_sizes[0] / F0;
    const int E = in_sizes[1] / 2;

    const int TB = 256;
    const int nb_scan = (n + SCAN_B - 1) / SCAN_B;

    // dtype detect + degree + CSR build
    k_detect<<<1, 32>>>((const int*)ei);
    k_zero_n<<<(n + TB - 1) / TB, TB>>>(n);
    k_deg<<<(E + TB - 1) / TB, TB>>>(ei, E);
    k_dinv<<<(n + TB - 1) / TB, TB>>>(n);
    k_scan1<<<nb_scan, SCAN_B>>>(n);
    k_scan2<<<1, MAX_PART>>>(nb_scan);
    k_scan3<<<(n + TB - 1) / TB, TB>>>(n, E);
    k_fill<<<(E + TB - 1) / TB, TB>>>(ei, E);
    k_zero_pool<<<(NG * HID + TB - 1) / TB, TB>>>();

    const int gGemm = (n + 31) / 32;
    const int gN16  = (n * 16 + TB - 1) / TB;

    // layer 1
    k_gemm<F0, false, false><<<gGemm, TB>>>(x, W1, n);
    k_gather<<<gN16, TB>>>(b1, n);
    // layer 2
    k_gemm<HID, true, true><<<gGemm, TB>>>(x, W2, n);
    k_gather<<<gN16, TB>>>(b2, n);
    // layer 3
    k_gemm<HID, true, true><<<gGemm, TB>>>(x, W3, n);
    k_gather<<<gN16, TB>>>(b3, n);

    // pooling + head
    int nstrips = (n + 63) / 64;
    k_pool<<<(nstrips * 16 + TB - 1) / TB, TB>>>(batch, n);
    k_final<<<1, NG>>>(Wl, bl, (float*)d_out);
}

// round 7
// speedup vs baseline: 3.2411x; 1.4481x over previous
#include <cuda_runtime.h>
#include <math.h>

#define F0   128
#define HID  64
#define NG   64
#define NC   10
#define MAXN 100000
#define MAXE 1600000
#define SCAN_B 512
#define MAX_PART 256

// ---- scratch (no allocs allowed) ----
__device__ int   g_is64;
__device__ int   g_idc [MAXN];          // in-degree (int, excl. self-loop)
__device__ float g_dinv[MAXN];
__device__ int   g_rowstart[MAXN + 1];
__device__ int   g_cursor[MAXN];
__device__ int   g_part[MAX_PART];
__device__ int2  g_cedge[MAXE];         // CSR slot: (src, float_as_int(norm))
__device__ float g_h   [MAXN * HID];    // h = act(in) @ W
__device__ float g_agg [MAXN * HID];    // layer output (pre-relu)
__device__ float g_pool[NG * HID];
__device__ float g_cnt [NG];

__device__ __forceinline__ int fetch_idx(const void* p, long long i) {
    if (g_is64) return (int)((const long long*)p)[i];
    return ((const int*)p)[i];
}

// ---------------- dtype detection (parallel) ----------------
__global__ void k_detect(const int* __restrict__ ei) {
    __shared__ int s[256];
    int acc = 0;
    for (int i = threadIdx.x; i < 1024; i += 256) acc |= ei[2 * i + 1];
    s[threadIdx.x] = acc;
    __syncthreads();
    for (int d = 128; d; d >>= 1) {
        if (threadIdx.x < d) s[threadIdx.x] |= s[threadIdx.x + d];
        __syncthreads();
    }
    if (threadIdx.x == 0) g_is64 = (s[0] == 0) ? 1 : 0;
}

// ---------------- degree ----------------
__global__ void k_zero_n(int n) {
    int i = blockIdx.x * blockDim.x + threadIdx.x;
    if (i < n) g_idc[i] = 0;
}
__global__ void k_deg(const void* __restrict__ ei, int e) {
    int i = blockIdx.x * blockDim.x + threadIdx.x;
    if (i < e) atomicAdd(&g_idc[fetch_idx(ei, (long long)e + i)], 1);
}
__global__ void k_dinv(int n) {
    int i = blockIdx.x * blockDim.x + threadIdx.x;
    if (i < n) g_dinv[i] = rsqrtf((float)(g_idc[i] + 1));
}

// ---------------- exclusive scan of g_idc -> g_rowstart ----------------
__global__ void k_scan1(int n) {
    __shared__ int s[SCAN_B];
    int i = blockIdx.x * SCAN_B + threadIdx.x;
    int v = (i < n) ? g_idc[i] : 0;
    s[threadIdx.x] = v;
    __syncthreads();
    int incl = v;
    #pragma unroll
    for (int d = 1; d < SCAN_B; d <<= 1) {
        int t = (threadIdx.x >= d) ? s[threadIdx.x - d] : 0;
        __syncthreads();
        incl += t;
        s[threadIdx.x] = incl;
        __syncthreads();
    }
    if (i < n) g_rowstart[i] = incl - v;           // block-local exclusive
    if (threadIdx.x == SCAN_B - 1) g_part[blockIdx.x] = incl;
}
__global__ void k_scan2(int nb) {
    __shared__ int s[MAX_PART];
    int v = (threadIdx.x < nb) ? g_part[threadIdx.x] : 0;
    s[threadIdx.x] = v;
    __syncthreads();
    int incl = v;
    #pragma unroll
    for (int d = 1; d < MAX_PART; d <<= 1) {
        int t = (threadIdx.x >= d) ? s[threadIdx.x - d] : 0;
        __syncthreads();
        incl += t;
        s[threadIdx.x] = incl;
        __syncthreads();
    }
    if (threadIdx.x < nb) g_part[threadIdx.x] = incl - v;   // exclusive
}
__global__ void k_scan3(int n, int e) {
    int i = blockIdx.x * blockDim.x + threadIdx.x;
    if (i < n) {
        int r = g_rowstart[i] + g_part[i / SCAN_B];
        g_rowstart[i] = r;
        g_cursor[i] = r;
    }
    if (i == 0) g_rowstart[n] = e;
}

// ---------------- CSR fill: compute norm, scatter (src,norm) ----------------
__global__ void k_fill(const void* __restrict__ ei, int e) {
    int i = blockIdx.x * blockDim.x + threadIdx.x;
    if (i < e) {
        int s = fetch_idx(ei, i);
        int d = fetch_idx(ei, (long long)e + i);
        int pos = atomicAdd(&g_cursor[d], 1);
        g_cedge[pos] = make_int2(s, __float_as_int(g_dinv[s] * g_dinv[d]));
    }
}

__global__ void k_zero_pool() {
    int i = blockIdx.x * blockDim.x + threadIdx.x;
    if (i < NG * HID) g_pool[i] = 0.0f;
    if (i < NG)       g_cnt[i]  = 0.0f;
}

// ---------------- GEMM v2: g_h = act(in) @ W, 4x4 register tiles ------------
// block: 64 rows x 64 cols; thread (tx,ty) computes rows ty*4+[0,4), cols tx*4+[0,4)
template<int F_IN, bool RELU, bool USE_AGG>
__global__ void __launch_bounds__(256) k_gemm(const float* __restrict__ in,
                                              const float* __restrict__ W, int n) {
    constexpr int KC = 32;
    __shared__ float  Ws[F_IN][HID];       // full weight resident
    __shared__ float4 xs4[64][KC / 4];     // k-chunk of x tile
    const float* srcp = USE_AGG ? g_agg : in;
    const int tid  = threadIdx.x;
    const int row0 = blockIdx.x * 64;
    const int tx = tid & 15;
    const int ty = tid >> 4;

    #pragma unroll 4
    for (int i = tid; i < F_IN * HID / 4; i += 256)
        ((float4*)Ws)[i] = ((const float4*)W)[i];

    float acc[4][4];
    #pragma unroll
    for (int r = 0; r < 4; r++)
        #pragma unroll
        for (int c = 0; c < 4; c++) acc[r][c] = 0.0f;

    for (int kc = 0; kc < F_IN; kc += KC) {
        __syncthreads();
        // stage x tile chunk: 64 rows x KC cols = 512 float4s
        #pragma unroll
        for (int i = tid; i < 64 * KC / 4; i += 256) {
            int r  = i / (KC / 4), kq = i % (KC / 4);
            int row = row0 + r;
            float4 v = make_float4(0.f, 0.f, 0.f, 0.f);
            if (row < n) {
                v = *(const float4*)(srcp + (size_t)row * F_IN + kc + kq * 4);
                if (RELU) {
                    v.x = fmaxf(v.x, 0.f); v.y = fmaxf(v.y, 0.f);
                    v.z = fmaxf(v.z, 0.f); v.w = fmaxf(v.w, 0.f);
                }
            }
            xs4[r][kq] = v;
        }
        __syncthreads();

        #pragma unroll
        for (int k = 0; k < KC; k++) {
            float4 wv = *(const float4*)&Ws[kc + k][tx * 4];
            float xr[4];
            #pragma unroll
            for (int r = 0; r < 4; r++)
                xr[r] = ((const float*)&xs4[ty * 4 + r][0])[k];
            #pragma unroll
            for (int r = 0; r < 4; r++) {
                acc[r][0] = fmaf(xr[r], wv.x, acc[r][0]);
                acc[r][1] = fmaf(xr[r], wv.y, acc[r][1]);
                acc[r][2] = fmaf(xr[r], wv.z, acc[r][2]);
                acc[r][3] = fmaf(xr[r], wv.w, acc[r][3]);
            }
        }
    }

    #pragma unroll
    for (int r = 0; r < 4; r++) {
        int row = row0 + ty * 4 + r;
        if (row < n)
            *(float4*)&g_h[(size_t)row * HID + tx * 4] =
                make_float4(acc[r][0], acc[r][1], acc[r][2], acc[r][3]);
    }
}

// ---------------- CSR gather: agg[i] = dinv_i^2*h[i] + b + sum norm*h[src] ---
__global__ void __launch_bounds__(256) k_gather(const float* __restrict__ b, int n) {
    int idx = blockIdx.x * blockDim.x + threadIdx.x;   // n*16 threads
    if (idx >= n * 16) return;
    int i = idx >> 4, q = idx & 15;
    int beg = g_rowstart[i], end = g_rowstart[i + 1];
    float di = g_dinv[i];
    float nm0 = di * di;
    float4 hh = ((const float4*)g_h)[idx];
    float4 bb = ((const float4*)b)[q];
    float4 acc;
    acc.x = fmaf(hh.x, nm0, bb.x);
    acc.y = fmaf(hh.y, nm0, bb.y);
    acc.z = fmaf(hh.z, nm0, bb.z);
    acc.w = fmaf(hh.w, nm0, bb.w);
    #pragma unroll 4
    for (int p = beg; p < end; p++) {
        int2 md = g_cedge[p];            // broadcast across 16 lanes
        float nm = __int_as_float(md.y);
        float4 v = ((const float4*)g_h)[md.x * 16 + q];
        acc.x = fmaf(v.x, nm, acc.x);
        acc.y = fmaf(v.y, nm, acc.y);
        acc.z = fmaf(v.z, nm, acc.z);
        acc.w = fmaf(v.w, nm, acc.w);
    }
    ((float4*)g_agg)[idx] = acc;
}

// ---------------- pooling: mean over sorted batch, relu on load -------------
__global__ void k_pool(const void* __restrict__ batch, int n) {
    int idx = blockIdx.x * blockDim.x + threadIdx.x;
    int nstrips = (n + 63) / 64;
    if (idx >= nstrips * 16) return;
    int strip = idx >> 4, q = idx & 15;
    int i0 = strip * 64;
    int i1 = min(i0 + 64, n);
    float4 acc = make_float4(0.f, 0.f, 0.f, 0.f);
    float cnt = 0.f;
    int gcur = fetch_idx(batch, i0);
    for (int i = i0; i < i1; i++) {
        int g = fetch_idx(batch, i);
        if (g != gcur) {
            float* pp = &g_pool[gcur * 64 + q * 4];
            atomicAdd(pp + 0, acc.x); atomicAdd(pp + 1, acc.y);
            atomicAdd(pp + 2, acc.z); atomicAdd(pp + 3, acc.w);
            if (q == 0) atomicAdd(&g_cnt[gcur], cnt);
            acc = make_float4(0.f, 0.f, 0.f, 0.f); cnt = 0.f; gcur = g;
        }
        float4 h = ((const float4*)g_agg)[i * 16 + q];
        acc.x += fmaxf(h.x, 0.f);
        acc.y += fmaxf(h.y, 0.f);
        acc.z += fmaxf(h.z, 0.f);
        acc.w += fmaxf(h.w, 0.f);
        cnt += 1.0f;
    }
    float* pp = &g_pool[gcur * 64 + q * 4];
    atomicAdd(pp + 0, acc.x); atomicAdd(pp + 1, acc.y);
    atomicAdd(pp + 2, acc.z); atomicAdd(pp + 3, acc.w);
    if (q == 0) atomicAdd(&g_cnt[gcur], cnt);
}

// ---------------- final: linear + softmax ----------------
__global__ void k_final(const float* __restrict__ Wl, const float* __restrict__ bl,
                        float* __restrict__ out) {
    int g = threadIdx.x;
    if (g >= NG) return;
    float inv = 1.0f / fmaxf(g_cnt[g], 1.0f);
    float logits[NC];
    #pragma unroll
    for (int c = 0; c < NC; c++) logits[c] = bl[c];
    for (int f = 0; f < HID; f++) {
        float p = g_pool[g * HID + f] * inv;
        #pragma unroll
        for (int c = 0; c < NC; c++) logits[c] = fmaf(p, Wl[f * NC + c], logits[c]);
    }
    float mx = logits[0];
    #pragma unroll
    for (int c = 1; c < NC; c++) mx = fmaxf(mx, logits[c]);
    float s = 0.0f;
    #pragma unroll
    for (int c = 0; c < NC; c++) { logits[c] = expf(logits[c] - mx); s += logits[c]; }
    float is = 1.0f / s;
    #pragma unroll
    for (int c = 0; c < NC; c++) out[g * NC + c] = logits[c] * is;
}

extern "C" void kernel_launch(void* const* d_in, const int* in_sizes, int n_in,
                              void* d_out, int out_size) {
    const float* x     = (const float*)d_in[0];
    const void*  ei    = d_in[1];
    const void*  batch = d_in[2];
    const float* W1 = (const float*)d_in[3];
    const float* b1 = (const float*)d_in[4];
    const float* W2 = (const float*)d_in[5];
    const float* b2 = (const float*)d_in[6];
    const float* W3 = (const float*)d_in[7];
    const float* b3 = (const float*)d_in[8];
    const float* Wl = (const float*)d_in[9];
    const float* bl = (const float*)d_in[10];

    const int n = in_sizes[0] / F0;
    const int E = in_sizes[1] / 2;

    const int TB = 256;
    const int nb_scan = (n + SCAN_B - 1) / SCAN_B;

    // dtype detect + degree + CSR build
    k_detect<<<1, 256>>>((const int*)ei);
    k_zero_n<<<(n + TB - 1) / TB, TB>>>(n);
    k_deg<<<(E + TB - 1) / TB, TB>>>(ei, E);
    k_dinv<<<(n + TB - 1) / TB, TB>>>(n);
    k_scan1<<<nb_scan, SCAN_B>>>(n);
    k_scan2<<<1, MAX_PART>>>(nb_scan);
    k_scan3<<<(n + TB - 1) / TB, TB>>>(n, E);
    k_fill<<<(E + TB - 1) / TB, TB>>>(ei, E);
    k_zero_pool<<<(NG * HID + TB - 1) / TB, TB>>>();

    const int gGemm = (n + 63) / 64;
    const int gN16  = (n * 16 + TB - 1) / TB;

    // layer 1
    k_gemm<F0, false, false><<<gGemm, TB>>>(x, W1, n);
    k_gather<<<gN16, TB>>>(b1, n);
    // layer 2
    k_gemm<HID, true, true><<<gGemm, TB>>>(x, W2, n);
    k_gather<<<gN16, TB>>>(b2, n);
    // layer 3
    k_gemm<HID, true, true><<<gGemm, TB>>>(x, W3, n);
    k_gather<<<gN16, TB>>>(b3, n);

    // pooling + head
    int nstrips = (n + 63) / 64;
    k_pool<<<(nstrips * 16 + TB - 1) / TB, TB>>>(batch, n);
    k_final<<<1, NG>>>(Wl, bl, (float*)d_out);
}

// round 8
// speedup vs baseline: 3.5441x; 1.0935x over previous
#include <cuda_runtime.h>
#include <cuda_fp16.h>
#include <math.h>

#define F0   128
#define HID  64
#define NG   64
#define NC   10
#define MAXN 100000
#define MAXE 1600000
#define SCAN_B 512
#define MAX_PART 256

// ---- scratch (no allocs allowed) ----
__device__ int    g_is64;
__device__ int    g_idc [MAXN];          // in-degree (int, excl. self-loop)
__device__ float  g_dinv[MAXN];
__device__ int    g_rowstart[MAXN + 1];
__device__ int    g_cursor[MAXN];
__device__ int    g_part[MAX_PART];
__device__ int2   g_cedge[MAXE];         // CSR slot: (src, float_as_int(norm))
__device__ __half g_h   [MAXN * HID];    // h = act(in) @ W   (fp16!)
__device__ float  g_agg [MAXN * HID];    // layer output (pre-relu, fp32)
__device__ float  g_pool[NG * HID];
__device__ float  g_cnt [NG];

__device__ __forceinline__ int fetch_idx(const void* p, long long i) {
    if (g_is64) return (int)((const long long*)p)[i];
    return ((const int*)p)[i];
}

// ---------------- dtype detection (parallel) ----------------
__global__ void k_detect(const int* __restrict__ ei) {
    __shared__ int s[256];
    int acc = 0;
    for (int i = threadIdx.x; i < 1024; i += 256) acc |= ei[2 * i + 1];
    s[threadIdx.x] = acc;
    __syncthreads();
    for (int d = 128; d; d >>= 1) {
        if (threadIdx.x < d) s[threadIdx.x] |= s[threadIdx.x + d];
        __syncthreads();
    }
    if (threadIdx.x == 0) g_is64 = (s[0] == 0) ? 1 : 0;
}

// ---------------- degree ----------------
__global__ void k_zero_n(int n) {
    int i = blockIdx.x * blockDim.x + threadIdx.x;
    if (i < n) g_idc[i] = 0;
}
__global__ void k_deg(const void* __restrict__ ei, int e) {
    int i = blockIdx.x * blockDim.x + threadIdx.x;
    if (i < e) atomicAdd(&g_idc[fetch_idx(ei, (long long)e + i)], 1);
}
__global__ void k_dinv(int n) {
    int i = blockIdx.x * blockDim.x + threadIdx.x;
    if (i < n) g_dinv[i] = rsqrtf((float)(g_idc[i] + 1));
}

// ---------------- exclusive scan of g_idc -> g_rowstart ----------------
__global__ void k_scan1(int n) {
    __shared__ int s[SCAN_B];
    int i = blockIdx.x * SCAN_B + threadIdx.x;
    int v = (i < n) ? g_idc[i] : 0;
    s[threadIdx.x] = v;
    __syncthreads();
    int incl = v;
    #pragma unroll
    for (int d = 1; d < SCAN_B; d <<= 1) {
        int t = (threadIdx.x >= d) ? s[threadIdx.x - d] : 0;
        __syncthreads();
        incl += t;
        s[threadIdx.x] = incl;
        __syncthreads();
    }
    if (i < n) g_rowstart[i] = incl - v;           // block-local exclusive
    if (threadIdx.x == SCAN_B - 1) g_part[blockIdx.x] = incl;
}
__global__ void k_scan2(int nb) {
    __shared__ int s[MAX_PART];
    int v = (threadIdx.x < nb) ? g_part[threadIdx.x] : 0;
    s[threadIdx.x] = v;
    __syncthreads();
    int incl = v;
    #pragma unroll
    for (int d = 1; d < MAX_PART; d <<= 1) {
        int t = (threadIdx.x >= d) ? s[threadIdx.x - d] : 0;
        __syncthreads();
        incl += t;
        s[threadIdx.x] = incl;
        __syncthreads();
    }
    if (threadIdx.x < nb) g_part[threadIdx.x] = incl - v;   // exclusive
}
__global__ void k_scan3(int n, int e) {
    int i = blockIdx.x * blockDim.x + threadIdx.x;
    if (i < n) {
        int r = g_rowstart[i] + g_part[i / SCAN_B];
        g_rowstart[i] = r;
        g_cursor[i] = r;
    }
    if (i == 0) g_rowstart[n] = e;
}

// ---------------- CSR fill: compute norm, scatter (src,norm) ----------------
__global__ void k_fill(const void* __restrict__ ei, int e) {
    int i = blockIdx.x * blockDim.x + threadIdx.x;
    if (i < e) {
        int s = fetch_idx(ei, i);
        int d = fetch_idx(ei, (long long)e + i);
        int pos = atomicAdd(&g_cursor[d], 1);
        g_cedge[pos] = make_int2(s, __float_as_int(g_dinv[s] * g_dinv[d]));
    }
}

__global__ void k_zero_pool() {
    int i = blockIdx.x * blockDim.x + threadIdx.x;
    if (i < NG * HID) g_pool[i] = 0.0f;
    if (i < NG)       g_cnt[i]  = 0.0f;
}

// ---------------- GEMM: g_h(fp16) = act(in) @ W, 4x4 register tiles ---------
template<int F_IN, bool RELU, bool USE_AGG>
__global__ void __launch_bounds__(256) k_gemm(const float* __restrict__ in,
                                              const float* __restrict__ W, int n) {
    constexpr int KC = 32;
    __shared__ float  Ws[F_IN][HID];       // full weight resident
    __shared__ float4 xs4[64][KC / 4];     // k-chunk of x tile
    const float* srcp = USE_AGG ? g_agg : in;
    const int tid  = threadIdx.x;
    const int row0 = blockIdx.x * 64;
    const int tx = tid & 15;
    const int ty = tid >> 4;

    #pragma unroll 4
    for (int i = tid; i < F_IN * HID / 4; i += 256)
        ((float4*)Ws)[i] = ((const float4*)W)[i];

    float acc[4][4];
    #pragma unroll
    for (int r = 0; r < 4; r++)
        #pragma unroll
        for (int c = 0; c < 4; c++) acc[r][c] = 0.0f;

    for (int kc = 0; kc < F_IN; kc += KC) {
        __syncthreads();
        #pragma unroll
        for (int i = tid; i < 64 * KC / 4; i += 256) {
            int r  = i / (KC / 4), kq = i % (KC / 4);
            int row = row0 + r;
            float4 v = make_float4(0.f, 0.f, 0.f, 0.f);
            if (row < n) {
                v = *(const float4*)(srcp + (size_t)row * F_IN + kc + kq * 4);
                if (RELU) {
                    v.x = fmaxf(v.x, 0.f); v.y = fmaxf(v.y, 0.f);
                    v.z = fmaxf(v.z, 0.f); v.w = fmaxf(v.w, 0.f);
                }
            }
            xs4[r][kq] = v;
        }
        __syncthreads();

        #pragma unroll
        for (int k = 0; k < KC; k++) {
            float4 wv = *(const float4*)&Ws[kc + k][tx * 4];
            float xr[4];
            #pragma unroll
            for (int r = 0; r < 4; r++)
                xr[r] = ((const float*)&xs4[ty * 4 + r][0])[k];
            #pragma unroll
            for (int r = 0; r < 4; r++) {
                acc[r][0] = fmaf(xr[r], wv.x, acc[r][0]);
                acc[r][1] = fmaf(xr[r], wv.y, acc[r][1]);
                acc[r][2] = fmaf(xr[r], wv.z, acc[r][2]);
                acc[r][3] = fmaf(xr[r], wv.w, acc[r][3]);
            }
        }
    }

    #pragma unroll
    for (int r = 0; r < 4; r++) {
        int row = row0 + ty * 4 + r;
        if (row < n) {
            __half2 p0 = __floats2half2_rn(acc[r][0], acc[r][1]);
            __half2 p1 = __floats2half2_rn(acc[r][2], acc[r][3]);
            uint2 pk;
            pk.x = *(unsigned int*)&p0;
            pk.y = *(unsigned int*)&p1;
            *(uint2*)&g_h[(size_t)row * HID + tx * 4] = pk;
        }
    }
}

// ---------------- CSR gather: agg[i] = dinv_i^2*h[i] + b + sum norm*h[src] ---
// 8 threads per node; each handles 8 feats (one LDG.128 of 8 halves per edge).
__global__ void __launch_bounds__(256) k_gather(const float* __restrict__ b, int n) {
    int idx = blockIdx.x * blockDim.x + threadIdx.x;   // n*8 threads
    if (idx >= n * 8) return;
    int i = idx >> 3, q = idx & 7;
    int beg = g_rowstart[i], end = g_rowstart[i + 1];
    float di = g_dinv[i];
    float nm0 = di * di;

    const uint4* hp = (const uint4*)g_h;   // 16B = 8 halves
    uint4 hs = hp[i * 8 + q];
    float2 s0 = __half22float2(*(const __half2*)&hs.x);
    float2 s1 = __half22float2(*(const __half2*)&hs.y);
    float2 s2 = __half22float2(*(const __half2*)&hs.z);
    float2 s3 = __half22float2(*(const __half2*)&hs.w);
    float4 b0 = ((const float4*)b)[q * 2 + 0];
    float4 b1 = ((const float4*)b)[q * 2 + 1];

    float a0 = fmaf(s0.x, nm0, b0.x), a1 = fmaf(s0.y, nm0, b0.y);
    float a2 = fmaf(s1.x, nm0, b0.z), a3 = fmaf(s1.y, nm0, b0.w);
    float a4 = fmaf(s2.x, nm0, b1.x), a5 = fmaf(s2.y, nm0, b1.y);
    float a6 = fmaf(s3.x, nm0, b1.z), a7 = fmaf(s3.y, nm0, b1.w);

    #pragma unroll 4
    for (int p = beg; p < end; p++) {
        int2 md = g_cedge[p];            // broadcast across 8 lanes
        float nm = __int_as_float(md.y);
        uint4 hv = hp[md.x * 8 + q];
        float2 f0 = __half22float2(*(const __half2*)&hv.x);
        float2 f1 = __half22float2(*(const __half2*)&hv.y);
        float2 f2 = __half22float2(*(const __half2*)&hv.z);
        float2 f3 = __half22float2(*(const __half2*)&hv.w);
        a0 = fmaf(f0.x, nm, a0); a1 = fmaf(f0.y, nm, a1);
        a2 = fmaf(f1.x, nm, a2); a3 = fmaf(f1.y, nm, a3);
        a4 = fmaf(f2.x, nm, a4); a5 = fmaf(f2.y, nm, a5);
        a6 = fmaf(f3.x, nm, a6); a7 = fmaf(f3.y, nm, a7);
    }
    float4* op = (float4*)&g_agg[(size_t)i * HID + q * 8];
    op[0] = make_float4(a0, a1, a2, a3);
    op[1] = make_float4(a4, a5, a6, a7);
}

// ---------------- pooling: mean over sorted batch, relu on load -------------
__global__ void k_pool(const void* __restrict__ batch, int n) {
    int idx = blockIdx.x * blockDim.x + threadIdx.x;
    int nstrips = (n + 63) / 64;
    if (idx >= nstrips * 16) return;
    int strip = idx >> 4, q = idx & 15;
    int i0 = strip * 64;
    int i1 = min(i0 + 64, n);
    float4 acc = make_float4(0.f, 0.f, 0.f, 0.f);
    float cnt = 0.f;
    int gcur = fetch_idx(batch, i0);
    for (int i = i0; i < i1; i++) {
        int g = fetch_idx(batch, i);
        if (g != gcur) {
            float* pp = &g_pool[gcur * 64 + q * 4];
            atomicAdd(pp + 0, acc.x); atomicAdd(pp + 1, acc.y);
            atomicAdd(pp + 2, acc.z); atomicAdd(pp + 3, acc.w);
            if (q == 0) atomicAdd(&g_cnt[gcur], cnt);
            acc = make_float4(0.f, 0.f, 0.f, 0.f); cnt = 0.f; gcur = g;
        }
        float4 h = ((const float4*)g_agg)[i * 16 + q];
        acc.x += fmaxf(h.x, 0.f);
        acc.y += fmaxf(h.y, 0.f);
        acc.z += fmaxf(h.z, 0.f);
        acc.w += fmaxf(h.w, 0.f);
        cnt += 1.0f;
    }
    float* pp = &g_pool[gcur * 64 + q * 4];
    atomicAdd(pp + 0, acc.x); atomicAdd(pp + 1, acc.y);
    atomicAdd(pp + 2, acc.z); atomicAdd(pp + 3, acc.w);
    if (q == 0) atomicAdd(&g_cnt[gcur], cnt);
}

// ---------------- final: linear + softmax ----------------
__global__ void k_final(const float* __restrict__ Wl, const float* __restrict__ bl,
                        float* __restrict__ out) {
    int g = threadIdx.x;
    if (g >= NG) return;
    float inv = 1.0f / fmaxf(g_cnt[g], 1.0f);
    float logits[NC];
    #pragma unroll
    for (int c = 0; c < NC; c++) logits[c] = bl[c];
    for (int f = 0; f < HID; f++) {
        float p = g_pool[g * HID + f] * inv;
        #pragma unroll
        for (int c = 0; c < NC; c++) logits[c] = fmaf(p, Wl[f * NC + c], logits[c]);
    }
    float mx = logits[0];
    #pragma unroll
    for (int c = 1; c < NC; c++) mx = fmaxf(mx, logits[c]);
    float s = 0.0f;
    #pragma unroll
    for (int c = 0; c < NC; c++) { logits[c] = expf(logits[c] - mx); s += logits[c]; }
    float is = 1.0f / s;
    #pragma unroll
    for (int c = 0; c < NC; c++) out[g * NC + c] = logits[c] * is;
}

extern "C" void kernel_launch(void* const* d_in, const int* in_sizes, int n_in,
                              void* d_out, int out_size) {
    const float* x     = (const float*)d_in[0];
    const void*  ei    = d_in[1];
    const void*  batch = d_in[2];
    const float* W1 = (const float*)d_in[3];
    const float* b1 = (const float*)d_in[4];
    const float* W2 = (const float*)d_in[5];
    const float* b2 = (const float*)d_in[6];
    const float* W3 = (const float*)d_in[7];
    const float* b3 = (const float*)d_in[8];
    const float* Wl = (const float*)d_in[9];
    const float* bl = (const float*)d_in[10];

    const int n = in_sizes[0] / F0;
    const int E = in_sizes[1] / 2;

    const int TB = 256;
    const int nb_scan = (n + SCAN_B - 1) / SCAN_B;

    // dtype detect + degree + CSR build
    k_detect<<<1, 256>>>((const int*)ei);
    k_zero_n<<<(n + TB - 1) / TB, TB>>>(n);
    k_deg<<<(E + TB - 1) / TB, TB>>>(ei, E);
    k_dinv<<<(n + TB - 1) / TB, TB>>>(n);
    k_scan1<<<nb_scan, SCAN_B>>>(n);
    k_scan2<<<1, MAX_PART>>>(nb_scan);
    k_scan3<<<(n + TB - 1) / TB, TB>>>(n, E);
    k_fill<<<(E + TB - 1) / TB, TB>>>(ei, E);
    k_zero_pool<<<(NG * HID + TB - 1) / TB, TB>>>();

    const int gGemm = (n + 63) / 64;
    const int gN8   = (n * 8 + TB - 1) / TB;

    // layer 1
    k_gemm<F0, false, false><<<gGemm, TB>>>(x, W1, n);
    k_gather<<<gN8, TB>>>(b1, n);
    // layer 2
    k_gemm<HID, true, true><<<gGemm, TB>>>(x, W2, n);
    k_gather<<<gN8, TB>>>(b2, n);
    // layer 3
    k_gemm<HID, true, true><<<gGemm, TB>>>(x, W3, n);
    k_gather<<<gN8, TB>>>(b3, n);

    // pooling + head
    int nstrips = (n + 63) / 64;
    k_pool<<<(nstrips * 16 + TB - 1) / TB, TB>>>(batch, n);
    k_final<<<1, NG>>>(Wl, bl, (float*)d_out);
}

// round 9
// speedup vs baseline: 3.5750x; 1.0087x over previous
#include <cuda_runtime.h>
#include <cuda_fp16.h>
#include <math.h>

#define F0   128
#define HID  64
#define NG   64
#define NC   10
#define MAXN 100000
#define MAXE 1600000
#define SCAN_B 512
#define MAX_PART 256

// ---- scratch (no allocs allowed) ----
__device__ int    g_is64;
__device__ int    g_idc [MAXN];          // in-degree (int, excl. self-loop)
__device__ float  g_dinv[MAXN];
__device__ int    g_rowstart[MAXN + 1];
__device__ int    g_cursor[MAXN];
__device__ int    g_part[MAX_PART];
__device__ int2   g_cedge[MAXE];         // CSR slot: (src, float_as_int(norm))
__device__ __half g_h   [MAXN * HID];    // h = act(in) @ W   (fp16)
__device__ float  g_agg [MAXN * HID];    // layer output (pre-relu, fp32)
__device__ float  g_pool[NG * HID];
__device__ float  g_cnt [NG];

__device__ __forceinline__ int fetch_idx(const void* p, long long i) {
    if (g_is64) return (int)((const long long*)p)[i];
    return ((const int*)p)[i];
}

// packed fp32x2 helpers (Blackwell FFMA2 via PTX)
#define FMA_F32X2(d, a, b, c) \
    asm("fma.rn.f32x2 %0, %1, %2, %3;" : "=l"(d) : "l"(a), "l"(b), "l"(c))
#define PACK2(out, v) \
    asm("mov.b64 %0, {%1, %1};" : "=l"(out) : "r"(__float_as_int(v)))
#define UNPACK2(lo, hi, in) \
    asm("mov.b64 {%0, %1}, %2;" : "=f"(lo), "=f"(hi) : "l"(in))

// ---------------- fused init: dtype detect + zero idc + zero pool ----------
__global__ void k_init(const int* __restrict__ ei, int n) {
    int i = blockIdx.x * blockDim.x + threadIdx.x;
    if (i < n) g_idc[i] = 0;
    if (i < NG * HID) g_pool[i] = 0.0f;
    if (i < NG) g_cnt[i] = 0.0f;
    if (blockIdx.x == 0) {
        __shared__ int s[256];
        int acc = 0;
        for (int j = threadIdx.x; j < 1024; j += 256) acc |= ei[2 * j + 1];
        s[threadIdx.x] = acc;
        __syncthreads();
        for (int d = 128; d; d >>= 1) {
            if (threadIdx.x < d) s[threadIdx.x] |= s[threadIdx.x + d];
            __syncthreads();
        }
        if (threadIdx.x == 0) g_is64 = (s[0] == 0) ? 1 : 0;
    }
}

__global__ void k_deg(const void* __restrict__ ei, int e) {
    int i = blockIdx.x * blockDim.x + threadIdx.x;
    if (i < e) atomicAdd(&g_idc[fetch_idx(ei, (long long)e + i)], 1);
}

// ---------------- scan (+ dinv fused) ----------------
__global__ void k_scan1(int n) {
    __shared__ int s[SCAN_B];
    int i = blockIdx.x * SCAN_B + threadIdx.x;
    int v = (i < n) ? g_idc[i] : 0;
    if (i < n) g_dinv[i] = rsqrtf((float)(v + 1));
    s[threadIdx.x] = v;
    __syncthreads();
    int incl = v;
    #pragma unroll
    for (int d = 1; d < SCAN_B; d <<= 1) {
        int t = (threadIdx.x >= d) ? s[threadIdx.x - d] : 0;
        __syncthreads();
        incl += t;
        s[threadIdx.x] = incl;
        __syncthreads();
    }
    if (i < n) g_rowstart[i] = incl - v;           // block-local exclusive
    if (threadIdx.x == SCAN_B - 1) g_part[blockIdx.x] = incl;
}
__global__ void k_scan2(int nb) {
    __shared__ int s[MAX_PART];
    int v = (threadIdx.x < nb) ? g_part[threadIdx.x] : 0;
    s[threadIdx.x] = v;
    __syncthreads();
    int incl = v;
    #pragma unroll
    for (int d = 1; d < MAX_PART; d <<= 1) {
        int t = (threadIdx.x >= d) ? s[threadIdx.x - d] : 0;
        __syncthreads();
        incl += t;
        s[threadIdx.x] = incl;
        __syncthreads();
    }
    if (threadIdx.x < nb) g_part[threadIdx.x] = incl - v;   // exclusive
}
__global__ void k_scan3(int n, int e) {
    int i = blockIdx.x * blockDim.x + threadIdx.x;
    if (i < n) {
        int r = g_rowstart[i] + g_part[i / SCAN_B];
        g_rowstart[i] = r;
        g_cursor[i] = r;
    }
    if (i == 0) g_rowstart[n] = e;
}

__global__ void k_fill(const void* __restrict__ ei, int e) {
    int i = blockIdx.x * blockDim.x + threadIdx.x;
    if (i < e) {
        int s = fetch_idx(ei, i);
        int d = fetch_idx(ei, (long long)e + i);
        int pos = atomicAdd(&g_cursor[d], 1);
        g_cedge[pos] = make_int2(s, __float_as_int(g_dinv[s] * g_dinv[d]));
    }
}

// ---------------- GEMM: g_h(fp16) = act(in) @ W, 4x4 tiles, FFMA2 ----------
template<int F_IN, bool RELU, bool USE_AGG>
__global__ void __launch_bounds__(256) k_gemm(const float* __restrict__ in,
                                              const float* __restrict__ W, int n) {
    constexpr int KC = 32;
    __shared__ float  Ws[F_IN][HID];       // full weight resident
    __shared__ float4 xs4[64][KC / 4];     // k-chunk of x tile
    const float* srcp = USE_AGG ? g_agg : in;
    const int tid  = threadIdx.x;
    const int row0 = blockIdx.x * 64;
    const int tx = tid & 15;
    const int ty = tid >> 4;

    #pragma unroll 4
    for (int i = tid; i < F_IN * HID / 4; i += 256)
        ((float4*)Ws)[i] = ((const float4*)W)[i];

    unsigned long long acc2[4][2];         // 4 rows x (2 packed col-pairs)
    #pragma unroll
    for (int r = 0; r < 4; r++) { acc2[r][0] = 0ull; acc2[r][1] = 0ull; }

    for (int kc = 0; kc < F_IN; kc += KC) {
        __syncthreads();
        #pragma unroll
        for (int i = tid; i < 64 * KC / 4; i += 256) {
            int r  = i / (KC / 4), kq = i % (KC / 4);
            int row = row0 + r;
            float4 v = make_float4(0.f, 0.f, 0.f, 0.f);
            if (row < n) {
                v = *(const float4*)(srcp + (size_t)row * F_IN + kc + kq * 4);
                if (RELU) {
                    v.x = fmaxf(v.x, 0.f); v.y = fmaxf(v.y, 0.f);
                    v.z = fmaxf(v.z, 0.f); v.w = fmaxf(v.w, 0.f);
                }
            }
            xs4[r][kq] = v;
        }
        __syncthreads();

        #pragma unroll
        for (int k = 0; k < KC; k++) {
            ulonglong2 wv = *(const ulonglong2*)&Ws[kc + k][tx * 4];
            #pragma unroll
            for (int r = 0; r < 4; r++) {
                float xr = ((const float*)&xs4[ty * 4 + r][0])[k];
                unsigned long long xp;
                PACK2(xp, xr);
                FMA_F32X2(acc2[r][0], xp, wv.x, acc2[r][0]);
                FMA_F32X2(acc2[r][1], xp, wv.y, acc2[r][1]);
            }
        }
    }

    #pragma unroll
    for (int r = 0; r < 4; r++) {
        int row = row0 + ty * 4 + r;
        if (row < n) {
            float c0, c1, c2, c3;
            UNPACK2(c0, c1, acc2[r][0]);
            UNPACK2(c2, c3, acc2[r][1]);
            __half2 p0 = __floats2half2_rn(c0, c1);
            __half2 p1 = __floats2half2_rn(c2, c3);
            uint2 pk;
            pk.x = *(unsigned int*)&p0;
            pk.y = *(unsigned int*)&p1;
            *(uint2*)&g_h[(size_t)row * HID + tx * 4] = pk;
        }
    }
}

// ---------------- CSR gather: agg[i] = dinv_i^2*h[i] + b + sum norm*h[src] ---
// 8 threads per node; each handles 8 feats (one LDG.128 of 8 halves per edge).
__global__ void __launch_bounds__(256) k_gather(const float* __restrict__ b, int n) {
    int idx = blockIdx.x * blockDim.x + threadIdx.x;   // n*8 threads
    if (idx >= n * 8) return;
    int i = idx >> 3, q = idx & 7;
    int beg = g_rowstart[i], end = g_rowstart[i + 1];
    float di = g_dinv[i];
    float nm0 = di * di;

    const uint4* hp = (const uint4*)g_h;   // 16B = 8 halves
    uint4 hs = hp[i * 8 + q];
    float2 s0 = __half22float2(*(const __half2*)&hs.x);
    float2 s1 = __half22float2(*(const __half2*)&hs.y);
    float2 s2 = __half22float2(*(const __half2*)&hs.z);
    float2 s3 = __half22float2(*(const __half2*)&hs.w);
    float4 b0 = ((const float4*)b)[q * 2 + 0];
    float4 b1 = ((const float4*)b)[q * 2 + 1];

    float a0 = fmaf(s0.x, nm0, b0.x), a1 = fmaf(s0.y, nm0, b0.y);
    float a2 = fmaf(s1.x, nm0, b0.z), a3 = fmaf(s1.y, nm0, b0.w);
    float a4 = fmaf(s2.x, nm0, b1.x), a5 = fmaf(s2.y, nm0, b1.y);
    float a6 = fmaf(s3.x, nm0, b1.z), a7 = fmaf(s3.y, nm0, b1.w);

    #pragma unroll 4
    for (int p = beg; p < end; p++) {
        int2 md = g_cedge[p];            // broadcast across 8 lanes
        float nm = __int_as_float(md.y);
        uint4 hv = hp[md.x * 8 + q];
        float2 f0 = __half22float2(*(const __half2*)&hv.x);
        float2 f1 = __half22float2(*(const __half2*)&hv.y);
        float2 f2 = __half22float2(*(const __half2*)&hv.z);
        float2 f3 = __half22float2(*(const __half2*)&hv.w);
        a0 = fmaf(f0.x, nm, a0); a1 = fmaf(f0.y, nm, a1);
        a2 = fmaf(f1.x, nm, a2); a3 = fmaf(f1.y, nm, a3);
        a4 = fmaf(f2.x, nm, a4); a5 = fmaf(f2.y, nm, a5);
        a6 = fmaf(f3.x, nm, a6); a7 = fmaf(f3.y, nm, a7);
    }
    float4* op = (float4*)&g_agg[(size_t)i * HID + q * 8];
    op[0] = make_float4(a0, a1, a2, a3);
    op[1] = make_float4(a4, a5, a6, a7);
}

// ---------------- pooling: mean over sorted batch, relu on load -------------
__global__ void k_pool(const void* __restrict__ batch, int n) {
    int idx = blockIdx.x * blockDim.x + threadIdx.x;
    int nstrips = (n + 63) / 64;
    if (idx >= nstrips * 16) return;
    int strip = idx >> 4, q = idx & 15;
    int i0 = strip * 64;
    int i1 = min(i0 + 64, n);
    float4 acc = make_float4(0.f, 0.f, 0.f, 0.f);
    float cnt = 0.f;
    int gcur = fetch_idx(batch, i0);
    for (int i = i0; i < i1; i++) {
        int g = fetch_idx(batch, i);
        if (g != gcur) {
            float* pp = &g_pool[gcur * 64 + q * 4];
            atomicAdd(pp + 0, acc.x); atomicAdd(pp + 1, acc.y);
            atomicAdd(pp + 2, acc.z); atomicAdd(pp + 3, acc.w);
            if (q == 0) atomicAdd(&g_cnt[gcur], cnt);
            acc = make_float4(0.f, 0.f, 0.f, 0.f); cnt = 0.f; gcur = g;
        }
        float4 h = ((const float4*)g_agg)[i * 16 + q];
        acc.x += fmaxf(h.x, 0.f);
        acc.y += fmaxf(h.y, 0.f);
        acc.z += fmaxf(h.z, 0.f);
        acc.w += fmaxf(h.w, 0.f);
        cnt += 1.0f;
    }
    float* pp = &g_pool[gcur * 64 + q * 4];
    atomicAdd(pp + 0, acc.x); atomicAdd(pp + 1, acc.y);
    atomicAdd(pp + 2, acc.z); atomicAdd(pp + 3, acc.w);
    if (q == 0) atomicAdd(&g_cnt[gcur], cnt);
}

// ---------------- final: linear + softmax ----------------
__global__ void k_final(const float* __restrict__ Wl, const float* __restrict__ bl,
                        float* __restrict__ out) {
    int g = threadIdx.x;
    if (g >= NG) return;
    float inv = 1.0f / fmaxf(g_cnt[g], 1.0f);
    float logits[NC];
    #pragma unroll
    for (int c = 0; c < NC; c++) logits[c] = bl[c];
    for (int f = 0; f < HID; f++) {
        float p = g_pool[g * HID + f] * inv;
        #pragma unroll
        for (int c = 0; c < NC; c++) logits[c] = fmaf(p, Wl[f * NC + c], logits[c]);
    }
    float mx = logits[0];
    #pragma unroll
    for (int c = 1; c < NC; c++) mx = fmaxf(mx, logits[c]);
    float s = 0.0f;
    #pragma unroll
    for (int c = 0; c < NC; c++) { logits[c] = expf(logits[c] - mx); s += logits[c]; }
    float is = 1.0f / s;
    #pragma unroll
    for (int c = 0; c < NC; c++) out[g * NC + c] = logits[c] * is;
}

extern "C" void kernel_launch(void* const* d_in, const int* in_sizes, int n_in,
                              void* d_out, int out_size) {
    const float* x     = (const float*)d_in[0];
    const void*  ei    = d_in[1];
    const void*  batch = d_in[2];
    const float* W1 = (const float*)d_in[3];
    const float* b1 = (const float*)d_in[4];
    const float* W2 = (const float*)d_in[5];
    const float* b2 = (const float*)d_in[6];
    const float* W3 = (const float*)d_in[7];
    const float* b3 = (const float*)d_in[8];
    const float* Wl = (const float*)d_in[9];
    const float* bl = (const float*)d_in[10];

    const int n = in_sizes[0] / F0;
    const int E = in_sizes[1] / 2;

    const int TB = 256;
    const int nb_scan = (n + SCAN_B - 1) / SCAN_B;

    // fused init + degree + CSR build  (6 launches)
    k_init<<<(n + TB - 1) / TB, TB>>>((const int*)ei, n);
    k_deg<<<(E + TB - 1) / TB, TB>>>(ei, E);
    k_scan1<<<nb_scan, SCAN_B>>>(n);
    k_scan2<<<1, MAX_PART>>>(nb_scan);
    k_scan3<<<(n + TB - 1) / TB, TB>>>(n, E);
    k_fill<<<(E + TB - 1) / TB, TB>>>(ei, E);

    const int gGemm = (n + 63) / 64;
    const int gN8   = (n * 8 + TB - 1) / TB;

    // layer 1
    k_gemm<F0, false, false><<<gGemm, TB>>>(x, W1, n);
    k_gather<<<gN8, TB>>>(b1, n);
    // layer 2
    k_gemm<HID, true, true><<<gGemm, TB>>>(x, W2, n);
    k_gather<<<gN8, TB>>>(b2, n);
    // layer 3
    k_gemm<HID, true, true><<<gGemm, TB>>>(x, W3, n);
    k_gather<<<gN8, TB>>>(b3, n);

    // pooling + head
    int nstrips = (n + 63) / 64;
    k_pool<<<(nstrips * 16 + TB - 1) / TB, TB>>>(batch, n);
    k_final<<<1, NG>>>(Wl, bl, (float*)d_out);
}

// round 10
// speedup vs baseline: 4.2504x; 1.1889x over previous
#include <cuda_runtime.h>
#include <cuda_fp16.h>
#include <math.h>

#define F0   128
#define HID  64
#define NG   64
#define NC   10
#define MAXN 100000
#define MAXE 1600000
#define SCAN_B 512
#define MAX_PART 256

// ---- scratch (no allocs allowed) ----
__device__ int    g_is64;
__device__ int    g_idc [MAXN];
__device__ float  g_dinv[MAXN];
__device__ int    g_rowstart[MAXN + 1];
__device__ int    g_cursor[MAXN];
__device__ int    g_part[MAX_PART];
__device__ int2   g_cedge[MAXE];         // CSR slot: (src, float_as_int(norm))
__device__ __half g_h   [MAXN * HID];    // h = act @ W   (fp16, pre-relu)
__device__ __half g_act [MAXN * HID];    // relu(agg)     (fp16)
__device__ float  g_pool[NG * HID];
__device__ float  g_cnt [NG];

__device__ __forceinline__ int fetch_idx(const void* p, long long i) {
    if (g_is64) return (int)((const long long*)p)[i];
    return ((const int*)p)[i];
}

// ---------------- fused init: dtype detect + zero idc + zero pool ----------
__global__ void k_init(const int* __restrict__ ei, int n) {
    int i = blockIdx.x * blockDim.x + threadIdx.x;
    if (i < n) g_idc[i] = 0;
    if (i < NG * HID) g_pool[i] = 0.0f;
    if (i < NG) g_cnt[i] = 0.0f;
    if (blockIdx.x == 0) {
        __shared__ int s[256];
        int acc = 0;
        for (int j = threadIdx.x; j < 1024; j += 256) acc |= ei[2 * j + 1];
        s[threadIdx.x] = acc;
        __syncthreads();
        for (int d = 128; d; d >>= 1) {
            if (threadIdx.x < d) s[threadIdx.x] |= s[threadIdx.x + d];
            __syncthreads();
        }
        if (threadIdx.x == 0) g_is64 = (s[0] == 0) ? 1 : 0;
    }
}

__global__ void k_deg(const void* __restrict__ ei, int e) {
    int i = blockIdx.x * blockDim.x + threadIdx.x;
    if (i < e) atomicAdd(&g_idc[fetch_idx(ei, (long long)e + i)], 1);
}

// ---------------- scan (+ dinv fused) ----------------
__global__ void k_scan1(int n) {
    __shared__ int s[SCAN_B];
    int i = blockIdx.x * SCAN_B + threadIdx.x;
    int v = (i < n) ? g_idc[i] : 0;
    if (i < n) g_dinv[i] = rsqrtf((float)(v + 1));
    s[threadIdx.x] = v;
    __syncthreads();
    int incl = v;
    #pragma unroll
    for (int d = 1; d < SCAN_B; d <<= 1) {
        int t = (threadIdx.x >= d) ? s[threadIdx.x - d] : 0;
        __syncthreads();
        incl += t;
        s[threadIdx.x] = incl;
        __syncthreads();
    }
    if (i < n) g_rowstart[i] = incl - v;
    if (threadIdx.x == SCAN_B - 1) g_part[blockIdx.x] = incl;
}
__global__ void k_scan2(int nb) {
    __shared__ int s[MAX_PART];
    int v = (threadIdx.x < nb) ? g_part[threadIdx.x] : 0;
    s[threadIdx.x] = v;
    __syncthreads();
    int incl = v;
    #pragma unroll
    for (int d = 1; d < MAX_PART; d <<= 1) {
        int t = (threadIdx.x >= d) ? s[threadIdx.x - d] : 0;
        __syncthreads();
        incl += t;
        s[threadIdx.x] = incl;
        __syncthreads();
    }
    if (threadIdx.x < nb) g_part[threadIdx.x] = incl - v;
}
__global__ void k_scan3(int n, int e) {
    int i = blockIdx.x * blockDim.x + threadIdx.x;
    if (i < n) {
        int r = g_rowstart[i] + g_part[i / SCAN_B];
        g_rowstart[i] = r;
        g_cursor[i] = r;
    }
    if (i == 0) g_rowstart[n] = e;
}

__global__ void k_fill(const void* __restrict__ ei, int e) {
    int i = blockIdx.x * blockDim.x + threadIdx.x;
    if (i < e) {
        int s = fetch_idx(ei, i);
        int d = fetch_idx(ei, (long long)e + i);
        int pos = atomicAdd(&g_cursor[d], 1);
        g_cedge[pos] = make_int2(s, __float_as_int(g_dinv[s] * g_dinv[d]));
    }
}

// ---------------- GEMM (tensor cores): g_h(fp16) = A @ W ---------------------
// A: layer1 = x (fp32, convert); layers 2/3 = g_act (fp16, copy).
// block: 64 rows x 64 cols, 8 warps, each warp 16 rows x 32 cols via
// mma.sync.m16n8k16 (A row-major, B col-major), fp32 accum.
template<int F_IN, bool FP16IN>
__global__ void __launch_bounds__(256) k_gemm(const float* __restrict__ in32,
                                              const float* __restrict__ W, int n) {
    constexpr int ST = F_IN + 8;               // smem stride in halves
    __shared__ __half As [64 * ST];
    __shared__ __half WTs[64 * ST];            // W^T: [n][k]
    const int tid   = threadIdx.x;
    const int row0  = blockIdx.x * 64;
    const int lane  = tid & 31;
    const int warp  = tid >> 5;
    const int wr    = warp >> 1;               // row group 0..3
    const int wc    = warp & 1;                // col group 0..1
    const int l4    = lane >> 2;
    const int l2    = (lane & 3) * 2;

    // stage A
    if (FP16IN) {
        #pragma unroll
        for (int i = tid; i < 64 * (F_IN / 8); i += 256) {
            int r = i / (F_IN / 8), c8 = i % (F_IN / 8);
            int row = row0 + r;
            uint4 v = make_uint4(0u, 0u, 0u, 0u);
            if (row < n) v = *(const uint4*)&g_act[(size_t)row * HID + c8 * 8];
            *(uint4*)&As[r * ST + c8 * 8] = v;
        }
    } else {
        #pragma unroll
        for (int i = tid; i < 64 * (F_IN / 4); i += 256) {
            int r = i / (F_IN / 4), kq = i % (F_IN / 4);
            int row = row0 + r;
            float4 v = make_float4(0.f, 0.f, 0.f, 0.f);
            if (row < n) v = *(const float4*)(in32 + (size_t)row * F_IN + kq * 4);
            __half2 p0 = __floats2half2_rn(v.x, v.y);
            __half2 p1 = __floats2half2_rn(v.z, v.w);
            uint2 pk;
            pk.x = *(unsigned int*)&p0;
            pk.y = *(unsigned int*)&p1;
            *(uint2*)&As[r * ST + kq * 4] = pk;
        }
    }
    // stage W^T (fp32 -> fp16, transpose)
    #pragma unroll 2
    for (int i = tid; i < 64 * F_IN; i += 256) {
        int nn = i & 63, k = i >> 6;
        WTs[nn * ST + k] = __float2half_rn(W[k * HID + nn]);
    }
    __syncthreads();

    float acc[4][4];
    #pragma unroll
    for (int t = 0; t < 4; t++)
        #pragma unroll
        for (int c = 0; c < 4; c++) acc[t][c] = 0.0f;

    #pragma unroll
    for (int ks = 0; ks < F_IN / 16; ks++) {
        const int abase = (wr * 16 + l4) * ST + ks * 16 + l2;
        unsigned int a0 = *(const unsigned int*)&As[abase];
        unsigned int a1 = *(const unsigned int*)&As[abase + 8 * ST];
        unsigned int a2 = *(const unsigned int*)&As[abase + 8];
        unsigned int a3 = *(const unsigned int*)&As[abase + 8 * ST + 8];
        #pragma unroll
        for (int nt = 0; nt < 4; nt++) {
            const int bbase = (wc * 32 + nt * 8 + l4) * ST + ks * 16 + l2;
            unsigned int b0 = *(const unsigned int*)&WTs[bbase];
            unsigned int b1 = *(const unsigned int*)&WTs[bbase + 8];
            asm volatile(
                "mma.sync.aligned.m16n8k16.row.col.f32.f16.f16.f32 "
                "{%0,%1,%2,%3}, {%4,%5,%6,%7}, {%8,%9}, {%0,%1,%2,%3};"
                : "+f"(acc[nt][0]), "+f"(acc[nt][1]), "+f"(acc[nt][2]), "+f"(acc[nt][3])
                : "r"(a0), "r"(a1), "r"(a2), "r"(a3), "r"(b0), "r"(b1));
        }
    }

    // store D as fp16 into g_h
    #pragma unroll
    for (int nt = 0; nt < 4; nt++) {
        int col = wc * 32 + nt * 8 + l2;
        int rA = row0 + wr * 16 + l4;
        int rB = rA + 8;
        __half2 pA = __floats2half2_rn(acc[nt][0], acc[nt][1]);
        __half2 pB = __floats2half2_rn(acc[nt][2], acc[nt][3]);
        if (rA < n) *(unsigned int*)&g_h[(size_t)rA * HID + col] = *(unsigned int*)&pA;
        if (rB < n) *(unsigned int*)&g_h[(size_t)rB * HID + col] = *(unsigned int*)&pB;
    }
}

// ---------------- CSR gather: act[i] = relu(dinv^2*h[i] + b + sum norm*h[s]) -
// 8 threads per node; each handles 8 feats.
__global__ void __launch_bounds__(256) k_gather(const float* __restrict__ b, int n) {
    int idx = blockIdx.x * blockDim.x + threadIdx.x;   // n*8 threads
    if (idx >= n * 8) return;
    int i = idx >> 3, q = idx & 7;
    int beg = g_rowstart[i], end = g_rowstart[i + 1];
    float di = g_dinv[i];
    float nm0 = di * di;

    const uint4* hp = (const uint4*)g_h;   // 16B = 8 halves
    uint4 hs = hp[i * 8 + q];
    float2 s0 = __half22float2(*(const __half2*)&hs.x);
    float2 s1 = __half22float2(*(const __half2*)&hs.y);
    float2 s2 = __half22float2(*(const __half2*)&hs.z);
    float2 s3 = __half22float2(*(const __half2*)&hs.w);
    float4 b0 = ((const float4*)b)[q * 2 + 0];
    float4 b1 = ((const float4*)b)[q * 2 + 1];

    float a0 = fmaf(s0.x, nm0, b0.x), a1 = fmaf(s0.y, nm0, b0.y);
    float a2 = fmaf(s1.x, nm0, b0.z), a3 = fmaf(s1.y, nm0, b0.w);
    float a4 = fmaf(s2.x, nm0, b1.x), a5 = fmaf(s2.y, nm0, b1.y);
    float a6 = fmaf(s3.x, nm0, b1.z), a7 = fmaf(s3.y, nm0, b1.w);

    #pragma unroll 4
    for (int p = beg; p < end; p++) {
        int2 md = g_cedge[p];            // broadcast across 8 lanes
        float nm = __int_as_float(md.y);
        uint4 hv = hp[md.x * 8 + q];
        float2 f0 = __half22float2(*(const __half2*)&hv.x);
        float2 f1 = __half22float2(*(const __half2*)&hv.y);
        float2 f2 = __half22float2(*(const __half2*)&hv.z);
        float2 f3 = __half22float2(*(const __half2*)&hv.w);
        a0 = fmaf(f0.x, nm, a0); a1 = fmaf(f0.y, nm, a1);
        a2 = fmaf(f1.x, nm, a2); a3 = fmaf(f1.y, nm, a3);
        a4 = fmaf(f2.x, nm, a4); a5 = fmaf(f2.y, nm, a5);
        a6 = fmaf(f3.x, nm, a6); a7 = fmaf(f3.y, nm, a7);
    }
    // relu + fp16 pack
    __half2 o0 = __floats2half2_rn(fmaxf(a0, 0.f), fmaxf(a1, 0.f));
    __half2 o1 = __floats2half2_rn(fmaxf(a2, 0.f), fmaxf(a3, 0.f));
    __half2 o2 = __floats2half2_rn(fmaxf(a4, 0.f), fmaxf(a5, 0.f));
    __half2 o3 = __floats2half2_rn(fmaxf(a6, 0.f), fmaxf(a7, 0.f));
    uint4 pk;
    pk.x = *(unsigned int*)&o0; pk.y = *(unsigned int*)&o1;
    pk.z = *(unsigned int*)&o2; pk.w = *(unsigned int*)&o3;
    ((uint4*)g_act)[idx] = pk;
}

// ---------------- pooling: mean over sorted batch (g_act already relu'd) ----
__global__ void k_pool(const void* __restrict__ batch, int n) {
    int idx = blockIdx.x * blockDim.x + threadIdx.x;
    int nstrips = (n + 63) / 64;
    if (idx >= nstrips * 8) return;
    int strip = idx >> 3, q = idx & 7;
    int i0 = strip * 64;
    int i1 = min(i0 + 64, n);
    float a0 = 0, a1 = 0, a2 = 0, a3 = 0, a4 = 0, a5 = 0, a6 = 0, a7 = 0;
    float cnt = 0.f;
    int gcur = fetch_idx(batch, i0);
    const uint4* ap = (const uint4*)g_act;
    for (int i = i0; i < i1; i++) {
        int g = fetch_idx(batch, i);
        if (g != gcur) {
            float* pp = &g_pool[gcur * 64 + q * 8];
            atomicAdd(pp + 0, a0); atomicAdd(pp + 1, a1);
            atomicAdd(pp + 2, a2); atomicAdd(pp + 3, a3);
            atomicAdd(pp + 4, a4); atomicAdd(pp + 5, a5);
            atomicAdd(pp + 6, a6); atomicAdd(pp + 7, a7);
            if (q == 0) atomicAdd(&g_cnt[gcur], cnt);
            a0 = a1 = a2 = a3 = a4 = a5 = a6 = a7 = 0.f; cnt = 0.f; gcur = g;
        }
        uint4 hv = ap[i * 8 + q];
        float2 f0 = __half22float2(*(const __half2*)&hv.x);
        float2 f1 = __half22float2(*(const __half2*)&hv.y);
        float2 f2 = __half22float2(*(const __half2*)&hv.z);
        float2 f3 = __half22float2(*(const __half2*)&hv.w);
        a0 += f0.x; a1 += f0.y; a2 += f1.x; a3 += f1.y;
        a4 += f2.x; a5 += f2.y; a6 += f3.x; a7 += f3.y;
        cnt += 1.0f;
    }
    float* pp = &g_pool[gcur * 64 + q * 8];
    atomicAdd(pp + 0, a0); atomicAdd(pp + 1, a1);
    atomicAdd(pp + 2, a2); atomicAdd(pp + 3, a3);
    atomicAdd(pp + 4, a4); atomicAdd(pp + 5, a5);
    atomicAdd(pp + 6, a6); atomicAdd(pp + 7, a7);
    if (q == 0) atomicAdd(&g_cnt[gcur], cnt);
}

// ---------------- final: linear + softmax ----------------
__global__ void k_final(const float* __restrict__ Wl, const float* __restrict__ bl,
                        float* __restrict__ out) {
    int g = threadIdx.x;
    if (g >= NG) return;
    float inv = 1.0f / fmaxf(g_cnt[g], 1.0f);
    float logits[NC];
    #pragma unroll
    for (int c = 0; c < NC; c++) logits[c] = bl[c];
    for (int f = 0; f < HID; f++) {
        float p = g_pool[g * HID + f] * inv;
        #pragma unroll
        for (int c = 0; c < NC; c++) logits[c] = fmaf(p, Wl[f * NC + c], logits[c]);
    }
    float mx = logits[0];
    #pragma unroll
    for (int c = 1; c < NC; c++) mx = fmaxf(mx, logits[c]);
    float s = 0.0f;
    #pragma unroll
    for (int c = 0; c < NC; c++) { logits[c] = expf(logits[c] - mx); s += logits[c]; }
    float is = 1.0f / s;
    #pragma unroll
    for (int c = 0; c < NC; c++) out[g * NC + c] = logits[c] * is;
}

extern "C" void kernel_launch(void* const* d_in, const int* in_sizes, int n_in,
                              void* d_out, int out_size) {
    const float* x     = (const float*)d_in[0];
    const void*  ei    = d_in[1];
    const void*  batch = d_in[2];
    const float* W1 = (const float*)d_in[3];
    const float* b1 = (const float*)d_in[4];
    const float* W2 = (const float*)d_in[5];
    const float* b2 = (const float*)d_in[6];
    const float* W3 = (const float*)d_in[7];
    const float* b3 = (const float*)d_in[8];
    const float* Wl = (const float*)d_in[9];
    const float* bl = (const float*)d_in[10];

    const int n = in_sizes[0] / F0;
    const int E = in_sizes[1] / 2;

    const int TB = 256;
    const int nb_scan = (n + SCAN_B - 1) / SCAN_B;

    // init + degree + CSR build
    k_init<<<(n + TB - 1) / TB, TB>>>((const int*)ei, n);
    k_deg<<<(E + TB - 1) / TB, TB>>>(ei, E);
    k_scan1<<<nb_scan, SCAN_B>>>(n);
    k_scan2<<<1, MAX_PART>>>(nb_scan);
    k_scan3<<<(n + TB - 1) / TB, TB>>>(n, E);
    k_fill<<<(E + TB - 1) / TB, TB>>>(ei, E);

    const int gGemm = (n + 63) / 64;
    const int gN8   = (n * 8 + TB - 1) / TB;

    // layer 1
    k_gemm<F0, false><<<gGemm, TB>>>(x, W1, n);
    k_gather<<<gN8, TB>>>(b1, n);
    // layer 2
    k_gemm<HID, true><<<gGemm, TB>>>(x, W2, n);
    k_gather<<<gN8, TB>>>(b2, n);
    // layer 3
    k_gemm<HID, true><<<gGemm, TB>>>(x, W3, n);
    k_gather<<<gN8, TB>>>(b3, n);

    // pooling + head
    int nstrips = (n + 63) / 64;
    k_pool<<<(nstrips * 8 + TB - 1) / TB, TB>>>(batch, n);
    k_final<<<1, NG>>>(Wl, bl, (float*)d_out);
}